// round 6
// baseline (speedup 1.0000x reference)
#include <cuda_runtime.h>
#include <cuda_bf16.h>
#include <cstdint>

// Problem dims
#define BATCH 8192
#define INF   784
#define HID   4096
#define OUTF  10

// int8 limb layout: 3 limbs, each K padded 784 -> 896 (7 chunks of 128B)
#define KSB   896            // S (weight) row bytes
#define KXB   2688           // X row bytes = 3 * 896
#define LIMB_CH 7
#define NCH   21             // total K chunks (3 limbs x 7)

// GEMM1 tiling: CTA 128x128, 4 warps, warp tile 64x64, BK=128 int8
#define BM 128
#define BN 128
#define STAGES 3
#define ROWB  144            // smem row stride bytes (conflict-free for ldmatrix, 16B mult)
#define A_BYTES (BM * ROWB)  // 18432
#define B_BYTES (BN * ROWB)  // 18432
#define STAGE_BYTES (A_BYTES + B_BYTES)          // 36864
#define SM_MBAR   (STAGES * STAGE_BYTES)         // 110592
#define SMEM_TOTAL (SM_MBAR + 64)                // 110656 -> 2 CTAs/SM
#define TX_BYTES  (256 * 128)                    // bytes per stage (A+B payload)

// epilogue h smem: 128 rows x 132 floats (16B-aligned rows)
#define HS 132

// -------------------- scratch (allowed: __device__ globals) --------------------
__device__ __align__(128) signed char g_Xq[(size_t)BATCH * KXB];
__device__ __align__(128) signed char g_Sq[(size_t)HID * KSB];

// -------------------- PTX helpers (compute_100 baseline; sm_90 bulk ok) ------------
__device__ __forceinline__ uint32_t smem_u32(const void* p) {
    uint32_t a;
    asm("{ .reg .u64 t; cvta.to.shared.u64 t, %1; cvt.u32.u64 %0, t; }" : "=r"(a) : "l"(p));
    return a;
}
__device__ __forceinline__ void mbar_init(uint32_t a, uint32_t cnt) {
    asm volatile("mbarrier.init.shared.b64 [%0], %1;" :: "r"(a), "r"(cnt) : "memory");
}
__device__ __forceinline__ void mbar_expect_tx(uint32_t a, uint32_t bytes) {
    asm volatile("mbarrier.arrive.expect_tx.shared.b64 _, [%0], %1;"
                 :: "r"(a), "r"(bytes) : "memory");
}
__device__ __forceinline__ void mbar_wait(uint32_t a, uint32_t parity) {
    uint32_t done;
    asm volatile("{\n\t.reg .pred p;\n\t"
                 "mbarrier.try_wait.parity.acquire.cta.shared::cta.b64 p, [%1], %2;\n\t"
                 "selp.b32 %0, 1, 0, p;\n\t}"
                 : "=r"(done) : "r"(a), "r"(parity) : "memory");
    while (!done) {
        asm volatile("{\n\t.reg .pred p;\n\t"
                     "mbarrier.try_wait.parity.acquire.cta.shared::cta.b64 p, [%1], %2, 0x989680;\n\t"
                     "selp.b32 %0, 1, 0, p;\n\t}"
                     : "=r"(done) : "r"(a), "r"(parity) : "memory");
    }
}
__device__ __forceinline__ void bulk_g2s(uint32_t dst, const void* src, uint32_t bytes,
                                         uint32_t mbar) {
    asm volatile("cp.async.bulk.shared::cta.global.mbarrier::complete_tx::bytes "
                 "[%0], [%1], %2, [%3];"
                 :: "r"(dst), "l"(src), "r"(bytes), "r"(mbar) : "memory");
}
__device__ __forceinline__ void ldsm_x4(uint32_t& r0, uint32_t& r1, uint32_t& r2, uint32_t& r3,
                                        uint32_t addr) {
    asm volatile("ldmatrix.sync.aligned.m8n8.x4.shared.b16 {%0,%1,%2,%3}, [%4];"
                 : "=r"(r0), "=r"(r1), "=r"(r2), "=r"(r3) : "r"(addr));
}
__device__ __forceinline__ void imma16832(int* c, uint32_t a0, uint32_t a1, uint32_t a2,
                                          uint32_t a3, uint32_t b0, uint32_t b1) {
    asm volatile("mma.sync.aligned.m16n8k32.row.col.s32.s8.s8.s32 "
                 "{%0,%1,%2,%3}, {%4,%5,%6,%7}, {%8,%9}, {%0,%1,%2,%3};"
                 : "+r"(c[0]), "+r"(c[1]), "+r"(c[2]), "+r"(c[3])
                 : "r"(a0), "r"(a1), "r"(a2), "r"(a3), "r"(b0), "r"(b1));
}

// -------------------- prep kernels --------------------
// x = a*2^-4 + b*2^-11 + c*2^-18 + eps, |eps| <= 2^-19; limbs exact in int8.
__global__ void prep_x_kernel(const float* __restrict__ x) {
    size_t idx = (size_t)blockIdx.x * blockDim.x + threadIdx.x;
    size_t total = (size_t)BATCH * KXB;
    if (idx >= total) return;
    int row = (int)(idx / KXB);
    int col = (int)(idx % KXB);
    int limb = col / KSB;
    int k = col - limb * KSB;
    signed char v = 0;
    if (k < INF) {
        float f = x[(size_t)row * INF + k];
        float a = rintf(f * 16.0f);
        if (limb == 0) {
            v = (signed char)(int)a;
        } else {
            float r1 = fmaf(a, -0.0625f, f);
            float b = rintf(r1 * 2048.0f);
            if (limb == 1) {
                v = (signed char)(int)b;
            } else {
                float r2 = fmaf(b, -4.8828125e-4f, r1);
                float c = rintf(r2 * 262144.0f);
                v = (signed char)(int)c;
            }
        }
    }
    g_Xq[idx] = v;
}

__global__ void prep_w_kernel(const float* __restrict__ W1) {
    size_t idx = (size_t)blockIdx.x * blockDim.x + threadIdx.x;
    size_t total = (size_t)HID * KSB;
    if (idx >= total) return;
    int row = (int)(idx / KSB);
    int col = (int)(idx % KSB);
    signed char s = 0;
    if (col < INF) {
        float w = W1[(size_t)row * INF + col];
        s = (w > 0.0f) ? 1 : ((w < 0.0f) ? -1 : 0);
    }
    g_Sq[idx] = s;
}

__global__ void init_out_kernel(const float* __restrict__ b2, float* __restrict__ out) {
    int i = blockIdx.x * blockDim.x + threadIdx.x;
    if (i < BATCH * OUTF) out[i] = b2[i % OUTF];
}

// -------------------- GEMM1 + fused FC2 --------------------
__device__ __forceinline__ void load_chunk_bulk(uint32_t sbase, int stage, int kc,
                                                int m0, int n0, int tid, uint32_t mbar) {
    uint32_t sa = sbase + stage * STAGE_BYTES;
    uint32_t sb = sa + A_BYTES;
    int kcs = kc; if (kcs >= 2 * LIMB_CH) kcs -= 2 * LIMB_CH; else if (kcs >= LIMB_CH) kcs -= LIMB_CH;
    const signed char* gA = g_Xq + (size_t)m0 * KXB + (size_t)kc * 128;
    const signed char* gB = g_Sq + (size_t)n0 * KSB + (size_t)kcs * 128;
    // 128 threads: each issues one A row + one B row (128B each)
    bulk_g2s(sa + tid * ROWB, gA + (size_t)tid * KXB, 128, mbar);
    bulk_g2s(sb + tid * ROWB, gB + (size_t)tid * KSB, 128, mbar);
}

__global__ void __launch_bounds__(128, 2) gemm1_kernel(const float* __restrict__ b1,
                                                       const float* __restrict__ W2,
                                                       float* __restrict__ out) {
    extern __shared__ char dsm[];
    const int tid  = threadIdx.x;
    const int lane = tid & 31;
    const int wid  = tid >> 5;
    const int wm   = wid & 1;        // M offset wm*64
    const int wn   = (wid >> 1) & 1; // N offset wn*64
    const int m0 = blockIdx.x * BM;
    const int n0 = blockIdx.y * BN;
    const uint32_t sbase = smem_u32(dsm);
    const uint32_t mb = sbase + SM_MBAR;

    if (tid == 0) {
#pragma unroll
        for (int s = 0; s < STAGES; s++) mbar_init(mb + s * 8, 1);
    }
    __syncthreads();

    // per-thread ldmatrix base byte offsets (stride-144 rows, no swizzle)
    const uint32_t aoff0 = (uint32_t)((wm * 64 + (lane & 15)) * ROWB + (lane >> 4) * 16);
    const uint32_t boff0 = (uint32_t)((wn * 64 + (lane & 7) + ((lane >> 4) << 3)) * ROWB
                                      + ((lane >> 3) & 1) * 16);

    int acc[4][8][4];
#pragma unroll
    for (int mf = 0; mf < 4; mf++)
#pragma unroll
        for (int nf = 0; nf < 8; nf++)
#pragma unroll
            for (int i = 0; i < 4; i++) acc[mf][nf][i] = 0;

    // prologue: chunks 0,1
    if (tid == 0) { mbar_expect_tx(mb + 0, TX_BYTES); mbar_expect_tx(mb + 8, TX_BYTES); }
    __syncthreads();
    load_chunk_bulk(sbase, 0, 0, m0, n0, tid, mb + 0);
    load_chunk_bulk(sbase, 1, 1, m0, n0, tid, mb + 8);

    for (int j = 0; j < NCH; j++) {
        const int stage = j % STAGES;
        mbar_wait(mb + stage * 8, (uint32_t)((j / STAGES) & 1));
        __syncthreads();   // all threads consumed chunk j-1's slot & observed barrier

        int jn = j + 2;
        if (jn < NCH) {
            int sn = jn % STAGES;
            if (tid == 0) mbar_expect_tx(mb + sn * 8, TX_BYTES);
            load_chunk_bulk(sbase, sn, jn, m0, n0, tid, mb + sn * 8);
        }

        // limb boundary: shift accumulated value up by 2^7 (exact, no overflow)
        if (j == LIMB_CH || j == 2 * LIMB_CH) {
#pragma unroll
            for (int mf = 0; mf < 4; mf++)
#pragma unroll
                for (int nf = 0; nf < 8; nf++)
#pragma unroll
                    for (int i = 0; i < 4; i++) acc[mf][nf][i] <<= 7;
        }

        // compute chunk j (128 int8 of K = 4 k32 steps)
        uint32_t sa = sbase + stage * STAGE_BYTES;
        uint32_t sb = sa + A_BYTES;
#pragma unroll
        for (int kk = 0; kk < 4; kk++) {
            uint32_t af[4][4];
            uint32_t bf[8][2];
#pragma unroll
            for (int mf = 0; mf < 4; mf++) {
                uint32_t off = aoff0 + (uint32_t)(mf * 16 * ROWB + kk * 32);
                ldsm_x4(af[mf][0], af[mf][1], af[mf][2], af[mf][3], sa + off);
            }
#pragma unroll
            for (int p = 0; p < 4; p++) {
                uint32_t off = boff0 + (uint32_t)(p * 16 * ROWB + kk * 32);
                uint32_t r0, r1, r2, r3;
                ldsm_x4(r0, r1, r2, r3, sb + off);
                bf[2 * p][0] = r0;  bf[2 * p][1] = r1;
                bf[2 * p + 1][0] = r2; bf[2 * p + 1][1] = r3;
            }
#pragma unroll
            for (int mf = 0; mf < 4; mf++)
#pragma unroll
                for (int nf = 0; nf < 8; nf++)
                    imma16832(acc[mf][nf], af[mf][0], af[mf][1], af[mf][2], af[mf][3],
                              bf[nf][0], bf[nf][1]);
        }
    }

    // ---- epilogue: h tile -> smem (clip(acc*2^-18 + b1)), then fused fc2 partial ----
    __syncthreads();   // everyone done reading stage smem before overwrite
    float* hs = (float*)dsm;
    const float SCL = 3.814697265625e-06f;   // 2^-18
    const int rloc0 = wm * 64 + (lane >> 2);
    const int cloc0 = wn * 64 + (lane & 3) * 2;
#pragma unroll
    for (int mf = 0; mf < 4; mf++) {
#pragma unroll
        for (int nf = 0; nf < 8; nf++) {
            int cl = cloc0 + nf * 8;
            float bb0 = __ldg(b1 + n0 + cl), bb1 = __ldg(b1 + n0 + cl + 1);
#pragma unroll
            for (int half = 0; half < 2; half++) {
                int rl = rloc0 + mf * 16 + half * 8;
                float v0 = fmaf((float)acc[mf][nf][2 * half],     SCL, bb0);
                float v1 = fmaf((float)acc[mf][nf][2 * half + 1], SCL, bb1);
                v0 = fminf(1.0f, fmaxf(-1.0f, v0));
                v1 = fminf(1.0f, fmaxf(-1.0f, v1));
                *(float2*)(hs + rl * HS + cl) = make_float2(v0, v1);
            }
        }
    }
    __syncthreads();

    // fc2 partial: thread t owns row t; W2 loads are warp-uniform (broadcast)
    {
        float accf[OUTF];
#pragma unroll
        for (int o = 0; o < OUTF; o++) accf[o] = 0.0f;
        const float4* hv4 = (const float4*)(hs + tid * HS);
        const float4* W2v = (const float4*)W2;
        const int base = n0 >> 2;
#pragma unroll 4
        for (int c4 = 0; c4 < 32; c4++) {
            float4 h4 = hv4[c4];
#pragma unroll
            for (int o = 0; o < OUTF; o++) {
                float4 w = __ldg(&W2v[o * (HID / 4) + base + c4]);
                accf[o] += h4.x * w.x + h4.y * w.y + h4.z * w.z + h4.w * w.w;
            }
        }
        float* op = out + (size_t)(m0 + tid) * OUTF;
#pragma unroll
        for (int o = 0; o < OUTF; o++) atomicAdd(op + o, accf[o]);
    }
}

// -------------------- launch --------------------
extern "C" void kernel_launch(void* const* d_in, const int* in_sizes, int n_in,
                              void* d_out, int out_size) {
    const float* x  = (const float*)d_in[0];
    const float* W1 = (const float*)d_in[1];
    const float* b1 = (const float*)d_in[2];
    const float* W2 = (const float*)d_in[3];
    const float* b2 = (const float*)d_in[4];
    float* out = (float*)d_out;

    cudaFuncSetAttribute(gemm1_kernel, cudaFuncAttributeMaxDynamicSharedMemorySize, SMEM_TOTAL);

    init_out_kernel<<<(BATCH * OUTF + 255) / 256, 256>>>(b2, out);
    {
        size_t total = (size_t)BATCH * KXB;
        prep_x_kernel<<<(unsigned)((total + 255) / 256), 256>>>(x);
    }
    {
        size_t total = (size_t)HID * KSB;
        prep_w_kernel<<<(unsigned)((total + 255) / 256), 256>>>(W1);
    }
    gemm1_kernel<<<dim3(BATCH / BM, HID / BN), 128, SMEM_TOTAL>>>(b1, W2, out);
}

// round 7
// speedup vs baseline: 1.5252x; 1.5252x over previous
#include <cuda_runtime.h>
#include <cuda_bf16.h>
#include <cstdint>

// Problem dims
#define BATCH 8192
#define INF   784
#define HID   4096
#define OUTF  10

// int8 limb layout: 3 limbs, each K padded 784 -> 896 (7 chunks of 128B)
#define KSB   896            // S (weight) row bytes
#define KXB   2688           // X row bytes = 3 * 896
#define LIMB_CH 7
#define NCH   21             // total K chunks (3 limbs x 7)

// GEMM1 tiling: CTA 128x128, 8 warps as 2(M) x 4(N), warp tile 64x32, BK=128 int8
#define BM 128
#define BN 128
#define STAGES 3
#define A_BYTES (BM * 128)   // 16384
#define B_BYTES (BN * 128)   // 16384
#define STAGE_BYTES (A_BYTES + B_BYTES)          // 32768
#define SMEM_TOTAL  (STAGES * STAGE_BYTES)       // 98304 -> 2 CTAs/SM, 16 warps

// epilogue h smem: 128 rows x 132 floats
#define HS 132

// -------------------- scratch (allowed: __device__ globals) --------------------
__device__ __align__(128) signed char g_Xq[(size_t)BATCH * KXB];
__device__ __align__(128) signed char g_Sq[(size_t)HID * KSB];

// -------------------- PTX helpers (compute_100 baseline only) --------------------
__device__ __forceinline__ uint32_t smem_u32(const void* p) {
    uint32_t a;
    asm("{ .reg .u64 t; cvta.to.shared.u64 t, %1; cvt.u32.u64 %0, t; }" : "=r"(a) : "l"(p));
    return a;
}
__device__ __forceinline__ uint32_t swz128(uint32_t off) {
    return off ^ ((off >> 3) & 0x70u);
}
__device__ __forceinline__ void cp16(uint32_t dst, const void* src) {
    asm volatile("cp.async.cg.shared.global [%0], [%1], 16;\n" :: "r"(dst), "l"(src));
}
__device__ __forceinline__ void cp_commit() {
    asm volatile("cp.async.commit_group;\n" ::: "memory");
}
__device__ __forceinline__ void ldsm_x4(uint32_t& r0, uint32_t& r1, uint32_t& r2, uint32_t& r3,
                                        uint32_t addr) {
    asm volatile("ldmatrix.sync.aligned.m8n8.x4.shared.b16 {%0,%1,%2,%3}, [%4];"
                 : "=r"(r0), "=r"(r1), "=r"(r2), "=r"(r3) : "r"(addr));
}
__device__ __forceinline__ void imma16832(int* c, uint32_t a0, uint32_t a1, uint32_t a2,
                                          uint32_t a3, uint32_t b0, uint32_t b1) {
    asm volatile("mma.sync.aligned.m16n8k32.row.col.s32.s8.s8.s32 "
                 "{%0,%1,%2,%3}, {%4,%5,%6,%7}, {%8,%9}, {%0,%1,%2,%3};"
                 : "+r"(c[0]), "+r"(c[1]), "+r"(c[2]), "+r"(c[3])
                 : "r"(a0), "r"(a1), "r"(a2), "r"(a3), "r"(b0), "r"(b1));
}

// -------------------- prep kernels --------------------
// x = a*2^-4 + b*2^-11 + c*2^-18 + eps, |eps| <= 2^-19; limbs exact in int8.
__global__ void prep_x_kernel(const float* __restrict__ x) {
    size_t idx = (size_t)blockIdx.x * blockDim.x + threadIdx.x;
    size_t total = (size_t)BATCH * KXB;
    if (idx >= total) return;
    int row = (int)(idx / KXB);
    int col = (int)(idx % KXB);
    int limb = col / KSB;
    int k = col - limb * KSB;
    signed char v = 0;
    if (k < INF) {
        float f = x[(size_t)row * INF + k];
        float a = rintf(f * 16.0f);
        if (limb == 0) {
            v = (signed char)(int)a;
        } else {
            float r1 = fmaf(a, -0.0625f, f);
            float b = rintf(r1 * 2048.0f);
            if (limb == 1) {
                v = (signed char)(int)b;
            } else {
                float r2 = fmaf(b, -4.8828125e-4f, r1);
                float c = rintf(r2 * 262144.0f);
                v = (signed char)(int)c;
            }
        }
    }
    g_Xq[idx] = v;
}

__global__ void prep_w_kernel(const float* __restrict__ W1) {
    size_t idx = (size_t)blockIdx.x * blockDim.x + threadIdx.x;
    size_t total = (size_t)HID * KSB;
    if (idx >= total) return;
    int row = (int)(idx / KSB);
    int col = (int)(idx % KSB);
    signed char s = 0;
    if (col < INF) {
        float w = W1[(size_t)row * INF + col];
        s = (w > 0.0f) ? 1 : ((w < 0.0f) ? -1 : 0);
    }
    g_Sq[idx] = s;
}

__global__ void init_out_kernel(const float* __restrict__ b2, float* __restrict__ out) {
    int i = blockIdx.x * blockDim.x + threadIdx.x;
    if (i < BATCH * OUTF) out[i] = b2[i % OUTF];
}

// -------------------- GEMM1 + fused FC2 --------------------
__device__ __forceinline__ void load_chunk(uint32_t sbase, int stage, int kc,
                                           int m0, int n0, int tid) {
    uint32_t sa = sbase + stage * STAGE_BYTES;
    uint32_t sb = sa + A_BYTES;
    int kcs = kc; if (kcs >= 2 * LIMB_CH) kcs -= 2 * LIMB_CH; else if (kcs >= LIMB_CH) kcs -= LIMB_CH;
    const signed char* gA = g_Xq + (size_t)m0 * KXB + (size_t)kc * 128;
    const signed char* gB = g_Sq + (size_t)n0 * KSB + (size_t)kcs * 128;
#pragma unroll
    for (int i = 0; i < 4; i++) {                 // A: 128 rows x 8 x 16B, 256 threads
        int id = i * 256 + tid;
        int r = id >> 3, s = id & 7;
        cp16(sa + swz128((uint32_t)(r * 128 + s * 16)), gA + (size_t)r * KXB + s * 16);
    }
#pragma unroll
    for (int i = 0; i < 4; i++) {                 // B: 128 rows x 8 x 16B
        int id = i * 256 + tid;
        int r = id >> 3, s = id & 7;
        cp16(sb + swz128((uint32_t)(r * 128 + s * 16)), gB + (size_t)r * KSB + s * 16);
    }
}

__global__ void __launch_bounds__(256, 2) gemm1_kernel(const float* __restrict__ b1,
                                                       const float* __restrict__ W2,
                                                       float* __restrict__ out) {
    extern __shared__ char dsm[];
    const int tid  = threadIdx.x;
    const int lane = tid & 31;
    const int wid  = tid >> 5;
    const int wm   = wid & 1;        // M offset wm*64
    const int wn   = wid >> 1;       // 0..3 -> N offset wn*32
    const int m0 = blockIdx.x * BM;
    const int n0 = blockIdx.y * BN;
    const uint32_t sbase = smem_u32(dsm);

    // per-thread ldmatrix base byte offsets (pre-swizzle); validated layout (R4/R5)
    const uint32_t aoff0 = (uint32_t)((wm * 64 + (lane & 15)) * 128 + (lane >> 4) * 16);
    const uint32_t boff0 = (uint32_t)((wn * 32 + (lane & 7) + ((lane >> 4) << 3)) * 128
                                      + ((lane >> 3) & 1) * 16);

    int acc[4][4][4];
#pragma unroll
    for (int mf = 0; mf < 4; mf++)
#pragma unroll
        for (int nf = 0; nf < 4; nf++)
#pragma unroll
            for (int i = 0; i < 4; i++) acc[mf][nf][i] = 0;

    // prologue
    load_chunk(sbase, 0, 0, m0, n0, tid); cp_commit();
    load_chunk(sbase, 1, 1, m0, n0, tid); cp_commit();

    int stage = 0;
    for (int j = 0; j < NCH; j++) {
        asm volatile("cp.async.wait_group 1;\n" ::: "memory");
        __syncthreads();

        int jn = j + 2;
        if (jn < NCH) {
            int sn = stage + 2; if (sn >= STAGES) sn -= STAGES;
            load_chunk(sbase, sn, jn, m0, n0, tid);
        }
        cp_commit();

        // limb boundary: shift accumulated value up by 2^7 (exact, no overflow)
        if (j == LIMB_CH || j == 2 * LIMB_CH) {
#pragma unroll
            for (int mf = 0; mf < 4; mf++)
#pragma unroll
                for (int nf = 0; nf < 4; nf++)
#pragma unroll
                    for (int i = 0; i < 4; i++) acc[mf][nf][i] <<= 7;
        }

        // compute chunk j (128 int8 of K = 4 k32 steps)
        uint32_t sa = sbase + stage * STAGE_BYTES;
        uint32_t sb = sa + A_BYTES;
#pragma unroll
        for (int kk = 0; kk < 4; kk++) {
            uint32_t af[4][4];
            uint32_t bf[4][2];
#pragma unroll
            for (int mf = 0; mf < 4; mf++) {
                uint32_t off = aoff0 + (uint32_t)(mf * 2048 + kk * 32);
                ldsm_x4(af[mf][0], af[mf][1], af[mf][2], af[mf][3], sa + swz128(off));
            }
#pragma unroll
            for (int p = 0; p < 2; p++) {
                uint32_t off = boff0 + (uint32_t)(p * 2048 + kk * 32);
                uint32_t r0, r1, r2, r3;
                ldsm_x4(r0, r1, r2, r3, sb + swz128(off));
                bf[2 * p][0] = r0;  bf[2 * p][1] = r1;
                bf[2 * p + 1][0] = r2; bf[2 * p + 1][1] = r3;
            }
#pragma unroll
            for (int mf = 0; mf < 4; mf++)
#pragma unroll
                for (int nf = 0; nf < 4; nf++)
                    imma16832(acc[mf][nf], af[mf][0], af[mf][1], af[mf][2], af[mf][3],
                              bf[nf][0], bf[nf][1]);
        }
        stage++; if (stage >= STAGES) stage = 0;
    }

    // ---- epilogue: h tile -> smem (clip(acc*2^-18 + b1)), then fused fc2 partial ----
    __syncthreads();   // everyone done reading stage smem before overwrite
    float* hs = (float*)dsm;
    const float SCL = 3.814697265625e-06f;   // 2^-18
    const int rloc0 = wm * 64 + (lane >> 2);
    const int cloc0 = wn * 32 + (lane & 3) * 2;
#pragma unroll
    for (int mf = 0; mf < 4; mf++) {
#pragma unroll
        for (int nf = 0; nf < 4; nf++) {
            int cl = cloc0 + nf * 8;
            float bb0 = __ldg(b1 + n0 + cl), bb1 = __ldg(b1 + n0 + cl + 1);
#pragma unroll
            for (int half = 0; half < 2; half++) {
                int rl = rloc0 + mf * 16 + half * 8;
                float v0 = fmaf((float)acc[mf][nf][2 * half],     SCL, bb0);
                float v1 = fmaf((float)acc[mf][nf][2 * half + 1], SCL, bb1);
                v0 = fminf(1.0f, fmaxf(-1.0f, v0));
                v1 = fminf(1.0f, fmaxf(-1.0f, v1));
                *(float2*)(hs + rl * HS + cl) = make_float2(v0, v1);
            }
        }
    }
    __syncthreads();

    // fc2 partial: 256 threads -> (row = tid&127, col-half = tid>>7) x 64 cols
    {
        const int row  = tid & 127;
        const int halfc = tid >> 7;          // 0 or 1
        float accf[OUTF];
#pragma unroll
        for (int o = 0; o < OUTF; o++) accf[o] = 0.0f;
        const float4* hv4 = (const float4*)(hs + row * HS + halfc * 64);
        const float4* W2v = (const float4*)W2;
        const int base = (n0 >> 2) + halfc * 16;
#pragma unroll 4
        for (int c4 = 0; c4 < 16; c4++) {
            float4 h4 = hv4[c4];
#pragma unroll
            for (int o = 0; o < OUTF; o++) {
                float4 w = __ldg(&W2v[o * (HID / 4) + base + c4]);
                accf[o] += h4.x * w.x + h4.y * w.y + h4.z * w.z + h4.w * w.w;
            }
        }
        float* op = out + (size_t)(m0 + row) * OUTF;
#pragma unroll
        for (int o = 0; o < OUTF; o++) atomicAdd(op + o, accf[o]);
    }
}

// -------------------- launch --------------------
extern "C" void kernel_launch(void* const* d_in, const int* in_sizes, int n_in,
                              void* d_out, int out_size) {
    const float* x  = (const float*)d_in[0];
    const float* W1 = (const float*)d_in[1];
    const float* b1 = (const float*)d_in[2];
    const float* W2 = (const float*)d_in[3];
    const float* b2 = (const float*)d_in[4];
    float* out = (float*)d_out;

    cudaFuncSetAttribute(gemm1_kernel, cudaFuncAttributeMaxDynamicSharedMemorySize, SMEM_TOTAL);

    init_out_kernel<<<(BATCH * OUTF + 255) / 256, 256>>>(b2, out);
    {
        size_t total = (size_t)BATCH * KXB;
        prep_x_kernel<<<(unsigned)((total + 255) / 256), 256>>>(x);
    }
    {
        size_t total = (size_t)HID * KSB;
        prep_w_kernel<<<(unsigned)((total + 255) / 256), 256>>>(W1);
    }
    gemm1_kernel<<<dim3(BATCH / BM, HID / BN), 256, SMEM_TOTAL>>>(b1, W2, out);
}

// round 8
// speedup vs baseline: 1.8613x; 1.2204x over previous
#include <cuda_runtime.h>
#include <cuda_bf16.h>
#include <cstdint>

// Problem dims
#define BATCH 8192
#define INF   784
#define HID   4096
#define OUTF  10

// int8 limb layout: 3 limbs, each K padded 784 -> 896 (7 chunks of 128B)
#define KSB   896            // S (weight) row bytes
#define KXB   2688           // X row bytes = 3 * 896
#define LIMB_CH 7
#define NCH   21             // total K chunks (3 limbs x 7)

// GEMM1 tiling: CTA 128x128, 4 warps as 2(M) x 2(N), warp tile 64x64, BK=128 int8
#define BM 128
#define BN 128
#define STAGES 3
#define A_BYTES (BM * 128)   // 16384
#define B_BYTES (BN * 128)   // 16384
#define STAGE_BYTES (A_BYTES + B_BYTES)          // 32768
#define SMEM_TOTAL  (STAGES * STAGE_BYTES)       // 98304 -> 2 CTAs/SM

// epilogue h smem: 128 rows x 132 floats
#define HS 132

// -------------------- scratch (allowed: __device__ globals) --------------------
__device__ __align__(128) signed char g_Xq[(size_t)BATCH * KXB];
__device__ __align__(128) signed char g_Sq[(size_t)HID * KSB];

// -------------------- PTX helpers (compute_100 baseline only) --------------------
__device__ __forceinline__ uint32_t smem_u32(const void* p) {
    uint32_t a;
    asm("{ .reg .u64 t; cvta.to.shared.u64 t, %1; cvt.u32.u64 %0, t; }" : "=r"(a) : "l"(p));
    return a;
}
__device__ __forceinline__ uint32_t swz128(uint32_t off) {
    return off ^ ((off >> 3) & 0x70u);
}
__device__ __forceinline__ void cp16(uint32_t dst, const void* src) {
    asm volatile("cp.async.cg.shared.global [%0], [%1], 16;\n" :: "r"(dst), "l"(src));
}
__device__ __forceinline__ void cp_commit() {
    asm volatile("cp.async.commit_group;\n" ::: "memory");
}
__device__ __forceinline__ void ldsm_x4(uint32_t& r0, uint32_t& r1, uint32_t& r2, uint32_t& r3,
                                        uint32_t addr) {
    asm volatile("ldmatrix.sync.aligned.m8n8.x4.shared.b16 {%0,%1,%2,%3}, [%4];"
                 : "=r"(r0), "=r"(r1), "=r"(r2), "=r"(r3) : "r"(addr));
}
__device__ __forceinline__ void imma16832(int* c, uint32_t a0, uint32_t a1, uint32_t a2,
                                          uint32_t a3, uint32_t b0, uint32_t b1) {
    asm volatile("mma.sync.aligned.m16n8k32.row.col.s32.s8.s8.s32 "
                 "{%0,%1,%2,%3}, {%4,%5,%6,%7}, {%8,%9}, {%0,%1,%2,%3};"
                 : "+r"(c[0]), "+r"(c[1]), "+r"(c[2]), "+r"(c[3])
                 : "r"(a0), "r"(a1), "r"(a2), "r"(a3), "r"(b0), "r"(b1));
}

// -------------------- prep kernels (vectorized) --------------------
// x = a*2^-4 + b*2^-11 + c*2^-18 + eps, |eps| <= 2^-19; limbs exact in int8.
// Thread handles 4 consecutive k for one row: one float4 read, three uchar4 writes.
#define KG 224               // 896/4 groups per row
__global__ void prep_x_kernel(const float* __restrict__ x) {
    int idx = blockIdx.x * blockDim.x + threadIdx.x;
    if (idx >= BATCH * KG) return;
    int row = idx / KG;
    int kg  = idx - row * KG;
    uchar4 la, lb, lc;
    if (kg < INF / 4) {
        float4 f4 = *(const float4*)(x + (size_t)row * INF + kg * 4);
        float fs[4] = {f4.x, f4.y, f4.z, f4.w};
        unsigned char va[4], vb[4], vc[4];
#pragma unroll
        for (int i = 0; i < 4; i++) {
            float f = fs[i];
            float a = rintf(f * 16.0f);
            float r1 = fmaf(a, -0.0625f, f);
            float b = rintf(r1 * 2048.0f);
            float r2 = fmaf(b, -4.8828125e-4f, r1);
            float c = rintf(r2 * 262144.0f);
            va[i] = (unsigned char)(signed char)(int)a;
            vb[i] = (unsigned char)(signed char)(int)b;
            vc[i] = (unsigned char)(signed char)(int)c;
        }
        la = make_uchar4(va[0], va[1], va[2], va[3]);
        lb = make_uchar4(vb[0], vb[1], vb[2], vb[3]);
        lc = make_uchar4(vc[0], vc[1], vc[2], vc[3]);
    } else {
        la = lb = lc = make_uchar4(0, 0, 0, 0);
    }
    size_t base = (size_t)row * KXB + kg * 4;
    *(uchar4*)(g_Xq + base)            = la;
    *(uchar4*)(g_Xq + base + KSB)      = lb;
    *(uchar4*)(g_Xq + base + 2 * KSB)  = lc;
}

__global__ void prep_w_kernel(const float* __restrict__ W1) {
    int idx = blockIdx.x * blockDim.x + threadIdx.x;
    if (idx >= HID * KG) return;
    int row = idx / KG;
    int kg  = idx - row * KG;
    uchar4 v = make_uchar4(0, 0, 0, 0);
    if (kg < INF / 4) {
        float4 w4 = *(const float4*)(W1 + (size_t)row * INF + kg * 4);
        float ws[4] = {w4.x, w4.y, w4.z, w4.w};
        unsigned char s[4];
#pragma unroll
        for (int i = 0; i < 4; i++) {
            float w = ws[i];
            s[i] = (unsigned char)(signed char)((w > 0.0f) ? 1 : ((w < 0.0f) ? -1 : 0));
        }
        v = make_uchar4(s[0], s[1], s[2], s[3]);
    }
    *(uchar4*)(g_Sq + (size_t)row * KSB + kg * 4) = v;
}

__global__ void init_out_kernel(const float* __restrict__ b2, float* __restrict__ out) {
    int i = blockIdx.x * blockDim.x + threadIdx.x;
    if (i < BATCH * OUTF) out[i] = b2[i % OUTF];
}

// -------------------- GEMM1 + fused FC2 --------------------
__device__ __forceinline__ void load_chunk(uint32_t sbase, int stage, int kc,
                                           int m0, int n0, int tid) {
    uint32_t sa = sbase + stage * STAGE_BYTES;
    uint32_t sb = sa + A_BYTES;
    int kcs = kc; if (kcs >= 2 * LIMB_CH) kcs -= 2 * LIMB_CH; else if (kcs >= LIMB_CH) kcs -= LIMB_CH;
    const signed char* gA = g_Xq + (size_t)m0 * KXB + (size_t)kc * 128;
    const signed char* gB = g_Sq + (size_t)n0 * KSB + (size_t)kcs * 128;
#pragma unroll
    for (int i = 0; i < 8; i++) {                 // A: 128 rows x 8 x 16B, 128 threads
        int id = i * 128 + tid;
        int r = id >> 3, s = id & 7;
        cp16(sa + swz128((uint32_t)(r * 128 + s * 16)), gA + (size_t)r * KXB + s * 16);
    }
#pragma unroll
    for (int i = 0; i < 8; i++) {                 // B: 128 rows x 8 x 16B
        int id = i * 128 + tid;
        int r = id >> 3, s = id & 7;
        cp16(sb + swz128((uint32_t)(r * 128 + s * 16)), gB + (size_t)r * KSB + s * 16);
    }
}

__global__ void __launch_bounds__(128, 2) gemm1_kernel(const float* __restrict__ b1,
                                                       const float* __restrict__ W2,
                                                       float* __restrict__ out) {
    extern __shared__ char dsm[];
    const int tid  = threadIdx.x;
    const int lane = tid & 31;
    const int wid  = tid >> 5;
    const int wm   = wid & 1;        // M offset wm*64
    const int wn   = (wid >> 1) & 1; // N offset wn*64
    const int m0 = blockIdx.x * BM;
    const int n0 = blockIdx.y * BN;
    const uint32_t sbase = smem_u32(dsm);

    // per-thread ldmatrix base byte offsets (pre-swizzle); validated (R4/R7)
    const uint32_t aoff0 = (uint32_t)((wm * 64 + (lane & 15)) * 128 + (lane >> 4) * 16);
    const uint32_t boff0 = (uint32_t)((wn * 64 + (lane & 7) + ((lane >> 4) << 3)) * 128
                                      + ((lane >> 3) & 1) * 16);

    int acc[4][8][4];
#pragma unroll
    for (int mf = 0; mf < 4; mf++)
#pragma unroll
        for (int nf = 0; nf < 8; nf++)
#pragma unroll
            for (int i = 0; i < 4; i++) acc[mf][nf][i] = 0;

    // prologue
    load_chunk(sbase, 0, 0, m0, n0, tid); cp_commit();
    load_chunk(sbase, 1, 1, m0, n0, tid); cp_commit();

    int stage = 0;
    for (int j = 0; j < NCH; j++) {
        asm volatile("cp.async.wait_group 1;\n" ::: "memory");
        __syncthreads();

        int jn = j + 2;
        if (jn < NCH) {
            int sn = stage + 2; if (sn >= STAGES) sn -= STAGES;
            load_chunk(sbase, sn, jn, m0, n0, tid);
        }
        cp_commit();

        // limb boundary: shift accumulated value up by 2^7 (exact, no overflow)
        if (j == LIMB_CH || j == 2 * LIMB_CH) {
#pragma unroll
            for (int mf = 0; mf < 4; mf++)
#pragma unroll
                for (int nf = 0; nf < 8; nf++)
#pragma unroll
                    for (int i = 0; i < 4; i++) acc[mf][nf][i] <<= 7;
        }

        // compute chunk j: 4 k32 steps, fragments double-buffered across kk
        uint32_t sa = sbase + stage * STAGE_BYTES;
        uint32_t sb = sa + A_BYTES;
        uint32_t af[2][4][4];
        uint32_t bf[2][8][2];
        // preload kk=0 fragments
#pragma unroll
        for (int mf = 0; mf < 4; mf++)
            ldsm_x4(af[0][mf][0], af[0][mf][1], af[0][mf][2], af[0][mf][3],
                    sa + swz128(aoff0 + (uint32_t)(mf * 2048)));
#pragma unroll
        for (int p = 0; p < 4; p++) {
            uint32_t r0, r1, r2, r3;
            ldsm_x4(r0, r1, r2, r3, sb + swz128(boff0 + (uint32_t)(p * 2048)));
            bf[0][2 * p][0] = r0;  bf[0][2 * p][1] = r1;
            bf[0][2 * p + 1][0] = r2; bf[0][2 * p + 1][1] = r3;
        }
#pragma unroll
        for (int kk = 0; kk < 4; kk++) {
            const int cur = kk & 1, nxt = cur ^ 1;
            if (kk < 3) {   // prefetch kk+1 fragments while issuing IMMAs
#pragma unroll
                for (int mf = 0; mf < 4; mf++)
                    ldsm_x4(af[nxt][mf][0], af[nxt][mf][1], af[nxt][mf][2], af[nxt][mf][3],
                            sa + swz128(aoff0 + (uint32_t)(mf * 2048 + (kk + 1) * 32)));
#pragma unroll
                for (int p = 0; p < 4; p++) {
                    uint32_t r0, r1, r2, r3;
                    ldsm_x4(r0, r1, r2, r3,
                            sb + swz128(boff0 + (uint32_t)(p * 2048 + (kk + 1) * 32)));
                    bf[nxt][2 * p][0] = r0;  bf[nxt][2 * p][1] = r1;
                    bf[nxt][2 * p + 1][0] = r2; bf[nxt][2 * p + 1][1] = r3;
                }
            }
#pragma unroll
            for (int mf = 0; mf < 4; mf++)
#pragma unroll
                for (int nf = 0; nf < 8; nf++)
                    imma16832(acc[mf][nf], af[cur][mf][0], af[cur][mf][1],
                              af[cur][mf][2], af[cur][mf][3],
                              bf[cur][nf][0], bf[cur][nf][1]);
        }
        stage++; if (stage >= STAGES) stage = 0;
    }

    // ---- epilogue: h tile -> smem (clip(acc*2^-18 + b1)), then fused fc2 partial ----
    __syncthreads();   // everyone done reading stage smem before overwrite
    float* hs = (float*)dsm;
    const float SCL = 3.814697265625e-06f;   // 2^-18
    const int rloc0 = wm * 64 + (lane >> 2);
    const int cloc0 = wn * 64 + (lane & 3) * 2;
#pragma unroll
    for (int mf = 0; mf < 4; mf++) {
#pragma unroll
        for (int nf = 0; nf < 8; nf++) {
            int cl = cloc0 + nf * 8;
            float bb0 = __ldg(b1 + n0 + cl), bb1 = __ldg(b1 + n0 + cl + 1);
#pragma unroll
            for (int half = 0; half < 2; half++) {
                int rl = rloc0 + mf * 16 + half * 8;
                float v0 = fmaf((float)acc[mf][nf][2 * half],     SCL, bb0);
                float v1 = fmaf((float)acc[mf][nf][2 * half + 1], SCL, bb1);
                v0 = fminf(1.0f, fmaxf(-1.0f, v0));
                v1 = fminf(1.0f, fmaxf(-1.0f, v1));
                *(float2*)(hs + rl * HS + cl) = make_float2(v0, v1);
            }
        }
    }
    __syncthreads();

    // fc2 partial: thread t owns row t; W2 loads warp-uniform (L1-resident)
    {
        float accf[OUTF];
#pragma unroll
        for (int o = 0; o < OUTF; o++) accf[o] = 0.0f;
        const float4* hv4 = (const float4*)(hs + tid * HS);
        const float4* W2v = (const float4*)W2;
        const int base = n0 >> 2;
#pragma unroll 4
        for (int c4 = 0; c4 < 32; c4++) {
            float4 h4 = hv4[c4];
#pragma unroll
            for (int o = 0; o < OUTF; o++) {
                float4 w = __ldg(&W2v[o * (HID / 4) + base + c4]);
                accf[o] += h4.x * w.x + h4.y * w.y + h4.z * w.z + h4.w * w.w;
            }
        }
        float* op = out + (size_t)(m0 + tid) * OUTF;
#pragma unroll
        for (int o = 0; o < OUTF; o++) atomicAdd(op + o, accf[o]);
    }
}

// -------------------- launch --------------------
extern "C" void kernel_launch(void* const* d_in, const int* in_sizes, int n_in,
                              void* d_out, int out_size) {
    const float* x  = (const float*)d_in[0];
    const float* W1 = (const float*)d_in[1];
    const float* b1 = (const float*)d_in[2];
    const float* W2 = (const float*)d_in[3];
    const float* b2 = (const float*)d_in[4];
    float* out = (float*)d_out;

    cudaFuncSetAttribute(gemm1_kernel, cudaFuncAttributeMaxDynamicSharedMemorySize, SMEM_TOTAL);

    init_out_kernel<<<(BATCH * OUTF + 255) / 256, 256>>>(b2, out);
    prep_x_kernel<<<(BATCH * KG + 255) / 256, 256>>>(x);
    prep_w_kernel<<<(HID * KG + 255) / 256, 256>>>(W1);
    gemm1_kernel<<<dim3(BATCH / BM, HID / BN), 128, SMEM_TOTAL>>>(b1, W2, out);
}

// round 9
// speedup vs baseline: 2.0282x; 1.0897x over previous
#include <cuda_runtime.h>
#include <cstdint>

// Problem dims
#define BATCH 8192
#define INF   784
#define HID   4096
#define OUTF  10

// int8 limb layout: 3 limbs, each K padded 784 -> 800 bytes; concat 2400 -> 19x128B chunks
#define KSB   800            // S (weight) row bytes (50 x 16B)
#define KXB   2432           // X row bytes = 19 chunks * 128 (2400 data + 32 pad)
#define NCH   19             // K chunks of 128B (76 k32-steps; steps 75 is zero pad)
// limb boundaries: before k32-step 25 (j=6,kk=1) and step 50 (j=12,kk=2)

// GEMM1 tiling: CTA 128x128, 4 warps as 2(M) x 2(N), warp tile 64x64, BK=128 int8
#define BM 128
#define BN 128
#define STAGES 3
#define A_BYTES (BM * 128)   // 16384
#define B_BYTES (BN * 128)   // 16384
#define STAGE_BYTES (A_BYTES + B_BYTES)          // 32768
#define SMEM_TOTAL  (STAGES * STAGE_BYTES)       // 98304 -> 2 CTAs/SM

// epilogue h smem: 128 rows x 132 floats
#define HS 132

// -------------------- scratch (allowed: __device__ globals) --------------------
__device__ __align__(128) signed char g_Xq[(size_t)BATCH * KXB];
__device__ __align__(128) signed char g_Sq[(size_t)HID * KSB + 1024];  // +pad for wrap overread

// -------------------- PTX helpers (compute_100 baseline only) --------------------
__device__ __forceinline__ uint32_t smem_u32(const void* p) {
    uint32_t a;
    asm("{ .reg .u64 t; cvta.to.shared.u64 t, %1; cvt.u32.u64 %0, t; }" : "=r"(a) : "l"(p));
    return a;
}
__device__ __forceinline__ uint32_t swz128(uint32_t off) {
    return off ^ ((off >> 3) & 0x70u);
}
__device__ __forceinline__ void cp16(uint32_t dst, const void* src) {
    asm volatile("cp.async.cg.shared.global [%0], [%1], 16;\n" :: "r"(dst), "l"(src));
}
__device__ __forceinline__ void cp_commit() {
    asm volatile("cp.async.commit_group;\n" ::: "memory");
}
__device__ __forceinline__ void ldsm_x4(uint32_t& r0, uint32_t& r1, uint32_t& r2, uint32_t& r3,
                                        uint32_t addr) {
    asm volatile("ldmatrix.sync.aligned.m8n8.x4.shared.b16 {%0,%1,%2,%3}, [%4];"
                 : "=r"(r0), "=r"(r1), "=r"(r2), "=r"(r3) : "r"(addr));
}
__device__ __forceinline__ void imma16832(int* c, uint32_t a0, uint32_t a1, uint32_t a2,
                                          uint32_t a3, uint32_t b0, uint32_t b1) {
    asm volatile("mma.sync.aligned.m16n8k32.row.col.s32.s8.s8.s32 "
                 "{%0,%1,%2,%3}, {%4,%5,%6,%7}, {%8,%9}, {%0,%1,%2,%3};"
                 : "+r"(c[0]), "+r"(c[1]), "+r"(c[2]), "+r"(c[3])
                 : "r"(a0), "r"(a1), "r"(a2), "r"(a3), "r"(b0), "r"(b1));
}

// -------------------- prep kernels (vectorized) --------------------
// x = a*2^-4 + b*2^-11 + c*2^-18 + eps, |eps| <= 2^-19; limbs exact in int8.
// 208 groups/row: kg<200 -> 3 limb writes at +0/+800/+1600; kg>=200 -> tail zero.
__global__ void prep_x_kernel(const float* __restrict__ x) {
    int idx = blockIdx.x * blockDim.x + threadIdx.x;
    if (idx >= BATCH * 208) return;
    int row = idx / 208;
    int kg  = idx - row * 208;
    if (kg >= 200) {   // tail bytes [2400, 2432)
        *(uchar4*)(g_Xq + (size_t)row * KXB + 2400 + (kg - 200) * 4) = make_uchar4(0, 0, 0, 0);
        return;
    }
    uchar4 la, lb, lc;
    if (kg < INF / 4) {
        float4 f4 = *(const float4*)(x + (size_t)row * INF + kg * 4);
        float fs[4] = {f4.x, f4.y, f4.z, f4.w};
        unsigned char va[4], vb[4], vc[4];
#pragma unroll
        for (int i = 0; i < 4; i++) {
            float f = fs[i];
            float a = rintf(f * 16.0f);
            float r1 = fmaf(a, -0.0625f, f);
            float b = rintf(r1 * 2048.0f);
            float r2 = fmaf(b, -4.8828125e-4f, r1);
            float c = rintf(r2 * 262144.0f);
            va[i] = (unsigned char)(signed char)(int)a;
            vb[i] = (unsigned char)(signed char)(int)b;
            vc[i] = (unsigned char)(signed char)(int)c;
        }
        la = make_uchar4(va[0], va[1], va[2], va[3]);
        lb = make_uchar4(vb[0], vb[1], vb[2], vb[3]);
        lc = make_uchar4(vc[0], vc[1], vc[2], vc[3]);
    } else {
        la = lb = lc = make_uchar4(0, 0, 0, 0);
    }
    size_t base = (size_t)row * KXB + kg * 4;
    *(uchar4*)(g_Xq + base)        = la;
    *(uchar4*)(g_Xq + base + 800)  = lb;
    *(uchar4*)(g_Xq + base + 1600) = lc;
}

__global__ void prep_w_kernel(const float* __restrict__ W1) {
    int idx = blockIdx.x * blockDim.x + threadIdx.x;
    if (idx >= HID * 200) return;
    int row = idx / 200;
    int kg  = idx - row * 200;
    uchar4 v = make_uchar4(0, 0, 0, 0);
    if (kg < INF / 4) {
        float4 w4 = *(const float4*)(W1 + (size_t)row * INF + kg * 4);
        float ws[4] = {w4.x, w4.y, w4.z, w4.w};
        unsigned char s[4];
#pragma unroll
        for (int i = 0; i < 4; i++) {
            float w = ws[i];
            s[i] = (unsigned char)(signed char)((w > 0.0f) ? 1 : ((w < 0.0f) ? -1 : 0));
        }
        v = make_uchar4(s[0], s[1], s[2], s[3]);
    }
    *(uchar4*)(g_Sq + (size_t)row * KSB + kg * 4) = v;
}

__global__ void init_out_kernel(const float* __restrict__ b2, float* __restrict__ out) {
    int i = blockIdx.x * blockDim.x + threadIdx.x;
    if (i < BATCH * OUTF) out[i] = b2[i % OUTF];
}

// -------------------- GEMM1 + fused FC2 --------------------
__device__ __forceinline__ void load_chunk(uint32_t sbase, int stage, int kc,
                                           int m0, int n0, int tid) {
    uint32_t sa = sbase + stage * STAGE_BYTES;
    uint32_t sb = sa + A_BYTES;
    const signed char* gA = g_Xq + (size_t)m0 * KXB + (size_t)kc * 128;
#pragma unroll
    for (int i = 0; i < 8; i++) {                 // A: 128 rows x 8 x 16B, 128 threads
        int id = i * 128 + tid;
        int r = id >> 3, s = id & 7;
        cp16(sa + swz128((uint32_t)(r * 128 + s * 16)), gA + (size_t)r * KXB + s * 16);
    }
#pragma unroll
    for (int i = 0; i < 8; i++) {                 // B: source wraps mod 800 per 16B block
        int id = i * 128 + tid;
        int r = id >> 3, s = id & 7;
        int g = kc * 128 + s * 16;
        int bsrc = (g >= 1600) ? (g - 1600) : ((g >= 800) ? (g - 800) : g);
        cp16(sb + swz128((uint32_t)(r * 128 + s * 16)),
             g_Sq + (size_t)(n0 + r) * KSB + bsrc);
    }
}

__global__ void __launch_bounds__(128, 2) gemm1_kernel(const float* __restrict__ b1,
                                                       const float* __restrict__ W2,
                                                       float* __restrict__ out) {
    extern __shared__ char dsm[];
    const int tid  = threadIdx.x;
    const int lane = tid & 31;
    const int wid  = tid >> 5;
    const int wm   = wid & 1;        // M offset wm*64
    const int wn   = (wid >> 1) & 1; // N offset wn*64
    const int m0 = blockIdx.x * BM;
    const int n0 = blockIdx.y * BN;
    const uint32_t sbase = smem_u32(dsm);

    // per-thread ldmatrix base byte offsets (pre-swizzle); validated (R4/R7/R8)
    const uint32_t aoff0 = (uint32_t)((wm * 64 + (lane & 15)) * 128 + (lane >> 4) * 16);
    const uint32_t boff0 = (uint32_t)((wn * 64 + (lane & 7) + ((lane >> 4) << 3)) * 128
                                      + ((lane >> 3) & 1) * 16);

    int acc[4][8][4];
#pragma unroll
    for (int mf = 0; mf < 4; mf++)
#pragma unroll
        for (int nf = 0; nf < 8; nf++)
#pragma unroll
            for (int i = 0; i < 4; i++) acc[mf][nf][i] = 0;

    // prologue
    load_chunk(sbase, 0, 0, m0, n0, tid); cp_commit();
    load_chunk(sbase, 1, 1, m0, n0, tid); cp_commit();

    int stage = 0;
    for (int j = 0; j < NCH; j++) {
        asm volatile("cp.async.wait_group 1;\n" ::: "memory");
        __syncthreads();

        uint32_t sa = sbase + stage * STAGE_BYTES;
        uint32_t sb = sa + A_BYTES;
        uint32_t af[2][4][4];
        uint32_t bf[2][8][2];
        // preload kk=0 fragments FIRST (ldsm latency overlaps cp.async issue below)
#pragma unroll
        for (int mf = 0; mf < 4; mf++)
            ldsm_x4(af[0][mf][0], af[0][mf][1], af[0][mf][2], af[0][mf][3],
                    sa + swz128(aoff0 + (uint32_t)(mf * 2048)));
#pragma unroll
        for (int p = 0; p < 4; p++) {
            uint32_t r0, r1, r2, r3;
            ldsm_x4(r0, r1, r2, r3, sb + swz128(boff0 + (uint32_t)(p * 2048)));
            bf[0][2 * p][0] = r0;  bf[0][2 * p][1] = r1;
            bf[0][2 * p + 1][0] = r2; bf[0][2 * p + 1][1] = r3;
        }

        int jn = j + 2;
        if (jn < NCH) {
            int sn = stage + 2; if (sn >= STAGES) sn -= STAGES;
            load_chunk(sbase, sn, jn, m0, n0, tid);
        }
        cp_commit();

#pragma unroll
        for (int kk = 0; kk < 4; kk++) {
            const int cur = kk & 1, nxt = cur ^ 1;
            // limb boundary (before k32-step 25 / 50): exact <<7 on accumulators
            if ((kk == 1 && j == 6) || (kk == 2 && j == 12)) {
#pragma unroll
                for (int mf = 0; mf < 4; mf++)
#pragma unroll
                    for (int nf = 0; nf < 8; nf++)
#pragma unroll
                        for (int i = 0; i < 4; i++) acc[mf][nf][i] <<= 7;
            }
            if (kk < 3) {   // prefetch kk+1 fragments while issuing IMMAs
#pragma unroll
                for (int mf = 0; mf < 4; mf++)
                    ldsm_x4(af[nxt][mf][0], af[nxt][mf][1], af[nxt][mf][2], af[nxt][mf][3],
                            sa + swz128(aoff0 + (uint32_t)(mf * 2048 + (kk + 1) * 32)));
#pragma unroll
                for (int p = 0; p < 4; p++) {
                    uint32_t r0, r1, r2, r3;
                    ldsm_x4(r0, r1, r2, r3,
                            sb + swz128(boff0 + (uint32_t)(p * 2048 + (kk + 1) * 32)));
                    bf[nxt][2 * p][0] = r0;  bf[nxt][2 * p][1] = r1;
                    bf[nxt][2 * p + 1][0] = r2; bf[nxt][2 * p + 1][1] = r3;
                }
            }
#pragma unroll
            for (int mf = 0; mf < 4; mf++)
#pragma unroll
                for (int nf = 0; nf < 8; nf++)
                    imma16832(acc[mf][nf], af[cur][mf][0], af[cur][mf][1],
                              af[cur][mf][2], af[cur][mf][3],
                              bf[cur][nf][0], bf[cur][nf][1]);
        }
        stage++; if (stage >= STAGES) stage = 0;
    }

    // ---- epilogue: h tile -> smem (clip(acc*2^-18 + b1)), then fused fc2 partial ----
    __syncthreads();   // everyone done reading stage smem before overwrite
    float* hs = (float*)dsm;
    const float SCL = 3.814697265625e-06f;   // 2^-18
    const int rloc0 = wm * 64 + (lane >> 2);
    const int cloc0 = wn * 64 + (lane & 3) * 2;
#pragma unroll
    for (int mf = 0; mf < 4; mf++) {
#pragma unroll
        for (int nf = 0; nf < 8; nf++) {
            int cl = cloc0 + nf * 8;
            float bb0 = __ldg(b1 + n0 + cl), bb1 = __ldg(b1 + n0 + cl + 1);
#pragma unroll
            for (int half = 0; half < 2; half++) {
                int rl = rloc0 + mf * 16 + half * 8;
                float v0 = fmaf((float)acc[mf][nf][2 * half],     SCL, bb0);
                float v1 = fmaf((float)acc[mf][nf][2 * half + 1], SCL, bb1);
                v0 = fminf(1.0f, fmaxf(-1.0f, v0));
                v1 = fminf(1.0f, fmaxf(-1.0f, v1));
                *(float2*)(hs + rl * HS + cl) = make_float2(v0, v1);
            }
        }
    }
    __syncthreads();

    // fc2 partial: thread t owns row t; W2 loads warp-uniform (L1-resident)
    {
        float accf[OUTF];
#pragma unroll
        for (int o = 0; o < OUTF; o++) accf[o] = 0.0f;
        const float4* hv4 = (const float4*)(hs + tid * HS);
        const float4* W2v = (const float4*)W2;
        const int base = n0 >> 2;
#pragma unroll 4
        for (int c4 = 0; c4 < 32; c4++) {
            float4 h4 = hv4[c4];
#pragma unroll
            for (int o = 0; o < OUTF; o++) {
                float4 w = __ldg(&W2v[o * (HID / 4) + base + c4]);
                accf[o] += h4.x * w.x + h4.y * w.y + h4.z * w.z + h4.w * w.w;
            }
        }
        float* op = out + (size_t)(m0 + tid) * OUTF;
#pragma unroll
        for (int o = 0; o < OUTF; o++) atomicAdd(op + o, accf[o]);
    }
}

// -------------------- launch --------------------
extern "C" void kernel_launch(void* const* d_in, const int* in_sizes, int n_in,
                              void* d_out, int out_size) {
    const float* x  = (const float*)d_in[0];
    const float* W1 = (const float*)d_in[1];
    const float* b1 = (const float*)d_in[2];
    const float* W2 = (const float*)d_in[3];
    const float* b2 = (const float*)d_in[4];
    float* out = (float*)d_out;

    cudaFuncSetAttribute(gemm1_kernel, cudaFuncAttributeMaxDynamicSharedMemorySize, SMEM_TOTAL);

    init_out_kernel<<<(BATCH * OUTF + 255) / 256, 256>>>(b2, out);
    prep_x_kernel<<<(BATCH * 208 + 255) / 256, 256>>>(x);
    prep_w_kernel<<<(HID * 200 + 255) / 256, 256>>>(W1);
    gemm1_kernel<<<dim3(BATCH / BM, HID / BN), 128, SMEM_TOTAL>>>(b1, W2, out);
}

// round 10
// speedup vs baseline: 2.5679x; 1.2661x over previous
#include <cuda_runtime.h>
#include <cstdint>

// Problem dims
#define BATCH 8192
#define INF   784
#define HID   4096
#define OUTF  10

// int8 2-limb layout: x = a/16 + b/4064 + eps, |eps| <= 1/8128
// limb a: bytes [0,800), limb b: [800,1600), zero pad [1600,1664)
#define KSB   800            // S (weight) row bytes (50 x 16B)
#define KXB   1664           // X row bytes = 13 chunks * 128
#define NCH   13             // K chunks of 128B (52 k32-steps; steps 50,51 hit zero pad)
// limb boundary: before k32-step 25 -> (j==6, kk==1): acc *= 254  (4064/16)

// GEMM1 tiling: CTA 128x128, 4 warps as 2(M) x 2(N), warp tile 64x64, BK=128 int8
#define BM 128
#define BN 128
#define STAGES 3
#define A_BYTES (BM * 128)   // 16384
#define B_BYTES (BN * 128)   // 16384
#define STAGE_BYTES (A_BYTES + B_BYTES)          // 32768
#define SMEM_TOTAL  (STAGES * STAGE_BYTES)       // 98304 -> 2 CTAs/SM

// epilogue h smem: 128 rows x 132 floats
#define HS 132

// -------------------- scratch (allowed: __device__ globals) --------------------
__device__ __align__(128) signed char g_Xq[(size_t)BATCH * KXB];
__device__ __align__(128) signed char g_Sq[(size_t)HID * KSB + 1024];  // +pad for wrap overread

// -------------------- PTX helpers (compute_100 baseline only) --------------------
__device__ __forceinline__ uint32_t smem_u32(const void* p) {
    uint32_t a;
    asm("{ .reg .u64 t; cvta.to.shared.u64 t, %1; cvt.u32.u64 %0, t; }" : "=r"(a) : "l"(p));
    return a;
}
__device__ __forceinline__ uint32_t swz128(uint32_t off) {
    return off ^ ((off >> 3) & 0x70u);
}
__device__ __forceinline__ void cp16(uint32_t dst, const void* src) {
    asm volatile("cp.async.cg.shared.global [%0], [%1], 16;\n" :: "r"(dst), "l"(src));
}
__device__ __forceinline__ void cp_commit() {
    asm volatile("cp.async.commit_group;\n" ::: "memory");
}
__device__ __forceinline__ void ldsm_x4(uint32_t& r0, uint32_t& r1, uint32_t& r2, uint32_t& r3,
                                        uint32_t addr) {
    asm volatile("ldmatrix.sync.aligned.m8n8.x4.shared.b16 {%0,%1,%2,%3}, [%4];"
                 : "=r"(r0), "=r"(r1), "=r"(r2), "=r"(r3) : "r"(addr));
}
__device__ __forceinline__ void imma16832(int* c, uint32_t a0, uint32_t a1, uint32_t a2,
                                          uint32_t a3, uint32_t b0, uint32_t b1) {
    asm volatile("mma.sync.aligned.m16n8k32.row.col.s32.s8.s8.s32 "
                 "{%0,%1,%2,%3}, {%4,%5,%6,%7}, {%8,%9}, {%0,%1,%2,%3};"
                 : "+r"(c[0]), "+r"(c[1]), "+r"(c[2]), "+r"(c[3])
                 : "r"(a0), "r"(a1), "r"(a2), "r"(a3), "r"(b0), "r"(b1));
}

// -------------------- prep kernels (vectorized) --------------------
// a = rint(16x) (|a|<=~88), r1 = x - a/16 (exact to fp rounding), b = rint(4064*r1) (|b|<=127)
// 216 groups/row: kg<200 -> limb writes at +0/+800; kg in [200,216) -> zero tail [1600,1664)
__global__ void prep_x_kernel(const float* __restrict__ x) {
    int idx = blockIdx.x * blockDim.x + threadIdx.x;
    if (idx >= BATCH * 216) return;
    int row = idx / 216;
    int kg  = idx - row * 216;
    if (kg >= 200) {   // tail bytes [1600, 1664)
        *(uchar4*)(g_Xq + (size_t)row * KXB + 1600 + (kg - 200) * 4) = make_uchar4(0, 0, 0, 0);
        return;
    }
    uchar4 la, lb;
    if (kg < INF / 4) {
        float4 f4 = *(const float4*)(x + (size_t)row * INF + kg * 4);
        float fs[4] = {f4.x, f4.y, f4.z, f4.w};
        unsigned char va[4], vb[4];
#pragma unroll
        for (int i = 0; i < 4; i++) {
            float f = fs[i];
            float a = rintf(f * 16.0f);
            float r1 = fmaf(a, -0.0625f, f);
            float b = rintf(r1 * 4064.0f);
            va[i] = (unsigned char)(signed char)(int)a;
            vb[i] = (unsigned char)(signed char)(int)b;
        }
        la = make_uchar4(va[0], va[1], va[2], va[3]);
        lb = make_uchar4(vb[0], vb[1], vb[2], vb[3]);
    } else {
        la = lb = make_uchar4(0, 0, 0, 0);
    }
    size_t base = (size_t)row * KXB + kg * 4;
    *(uchar4*)(g_Xq + base)        = la;
    *(uchar4*)(g_Xq + base + 800)  = lb;
}

__global__ void prep_w_kernel(const float* __restrict__ W1) {
    int idx = blockIdx.x * blockDim.x + threadIdx.x;
    if (idx >= HID * 200) return;
    int row = idx / 200;
    int kg  = idx - row * 200;
    uchar4 v = make_uchar4(0, 0, 0, 0);
    if (kg < INF / 4) {
        float4 w4 = *(const float4*)(W1 + (size_t)row * INF + kg * 4);
        float ws[4] = {w4.x, w4.y, w4.z, w4.w};
        unsigned char s[4];
#pragma unroll
        for (int i = 0; i < 4; i++) {
            float w = ws[i];
            s[i] = (unsigned char)(signed char)((w > 0.0f) ? 1 : ((w < 0.0f) ? -1 : 0));
        }
        v = make_uchar4(s[0], s[1], s[2], s[3]);
    }
    *(uchar4*)(g_Sq + (size_t)row * KSB + kg * 4) = v;
}

__global__ void init_out_kernel(const float* __restrict__ b2, float* __restrict__ out) {
    int i = blockIdx.x * blockDim.x + threadIdx.x;
    if (i < BATCH * OUTF) out[i] = b2[i % OUTF];
}

// -------------------- GEMM1 + fused FC2 --------------------
__device__ __forceinline__ void load_chunk(uint32_t sbase, int stage, int kc,
                                           int m0, int n0, int tid) {
    uint32_t sa = sbase + stage * STAGE_BYTES;
    uint32_t sb = sa + A_BYTES;
    const signed char* gA = g_Xq + (size_t)m0 * KXB + (size_t)kc * 128;
#pragma unroll
    for (int i = 0; i < 8; i++) {                 // A: 128 rows x 8 x 16B, 128 threads
        int id = i * 128 + tid;
        int r = id >> 3, s = id & 7;
        cp16(sa + swz128((uint32_t)(r * 128 + s * 16)), gA + (size_t)r * KXB + s * 16);
    }
#pragma unroll
    for (int i = 0; i < 8; i++) {                 // B: source wraps mod 800 per 16B block
        int id = i * 128 + tid;
        int r = id >> 3, s = id & 7;
        int g = kc * 128 + s * 16;
        int bsrc = (g >= 1600) ? (g - 1600) : ((g >= 800) ? (g - 800) : g);
        cp16(sb + swz128((uint32_t)(r * 128 + s * 16)),
             g_Sq + (size_t)(n0 + r) * KSB + bsrc);
    }
}

__global__ void __launch_bounds__(128, 2) gemm1_kernel(const float* __restrict__ b1,
                                                       const float* __restrict__ W2,
                                                       float* __restrict__ out) {
    extern __shared__ char dsm[];
    const int tid  = threadIdx.x;
    const int lane = tid & 31;
    const int wid  = tid >> 5;
    const int wm   = wid & 1;        // M offset wm*64
    const int wn   = (wid >> 1) & 1; // N offset wn*64
    const int m0 = blockIdx.x * BM;
    const int n0 = blockIdx.y * BN;
    const uint32_t sbase = smem_u32(dsm);

    // per-thread ldmatrix base byte offsets (pre-swizzle); validated (R4..R9)
    const uint32_t aoff0 = (uint32_t)((wm * 64 + (lane & 15)) * 128 + (lane >> 4) * 16);
    const uint32_t boff0 = (uint32_t)((wn * 64 + (lane & 7) + ((lane >> 4) << 3)) * 128
                                      + ((lane >> 3) & 1) * 16);

    int acc[4][8][4];
#pragma unroll
    for (int mf = 0; mf < 4; mf++)
#pragma unroll
        for (int nf = 0; nf < 8; nf++)
#pragma unroll
            for (int i = 0; i < 4; i++) acc[mf][nf][i] = 0;

    // prologue
    load_chunk(sbase, 0, 0, m0, n0, tid); cp_commit();
    load_chunk(sbase, 1, 1, m0, n0, tid); cp_commit();

    int stage = 0;
    for (int j = 0; j < NCH; j++) {
        asm volatile("cp.async.wait_group 1;\n" ::: "memory");
        __syncthreads();

        uint32_t sa = sbase + stage * STAGE_BYTES;
        uint32_t sb = sa + A_BYTES;
        uint32_t af[2][4][4];
        uint32_t bf[2][8][2];
        // preload kk=0 fragments FIRST (ldsm latency overlaps cp.async issue below)
#pragma unroll
        for (int mf = 0; mf < 4; mf++)
            ldsm_x4(af[0][mf][0], af[0][mf][1], af[0][mf][2], af[0][mf][3],
                    sa + swz128(aoff0 + (uint32_t)(mf * 2048)));
#pragma unroll
        for (int p = 0; p < 4; p++) {
            uint32_t r0, r1, r2, r3;
            ldsm_x4(r0, r1, r2, r3, sb + swz128(boff0 + (uint32_t)(p * 2048)));
            bf[0][2 * p][0] = r0;  bf[0][2 * p][1] = r1;
            bf[0][2 * p + 1][0] = r2; bf[0][2 * p + 1][1] = r3;
        }

        int jn = j + 2;
        if (jn < NCH) {
            int sn = stage + 2; if (sn >= STAGES) sn -= STAGES;
            load_chunk(sbase, sn, jn, m0, n0, tid);
        }
        cp_commit();

#pragma unroll
        for (int kk = 0; kk < 4; kk++) {
            const int cur = kk & 1, nxt = cur ^ 1;
            // limb boundary before k32-step 25: acc *= 254 (= 4064/16, exact in s32)
            if (kk == 1 && j == 6) {
#pragma unroll
                for (int mf = 0; mf < 4; mf++)
#pragma unroll
                    for (int nf = 0; nf < 8; nf++)
#pragma unroll
                        for (int i = 0; i < 4; i++) acc[mf][nf][i] *= 254;
            }
            if (kk < 3) {   // prefetch kk+1 fragments while issuing IMMAs
#pragma unroll
                for (int mf = 0; mf < 4; mf++)
                    ldsm_x4(af[nxt][mf][0], af[nxt][mf][1], af[nxt][mf][2], af[nxt][mf][3],
                            sa + swz128(aoff0 + (uint32_t)(mf * 2048 + (kk + 1) * 32)));
#pragma unroll
                for (int p = 0; p < 4; p++) {
                    uint32_t r0, r1, r2, r3;
                    ldsm_x4(r0, r1, r2, r3,
                            sb + swz128(boff0 + (uint32_t)(p * 2048 + (kk + 1) * 32)));
                    bf[nxt][2 * p][0] = r0;  bf[nxt][2 * p][1] = r1;
                    bf[nxt][2 * p + 1][0] = r2; bf[nxt][2 * p + 1][1] = r3;
                }
            }
#pragma unroll
            for (int mf = 0; mf < 4; mf++)
#pragma unroll
                for (int nf = 0; nf < 8; nf++)
                    imma16832(acc[mf][nf], af[cur][mf][0], af[cur][mf][1],
                              af[cur][mf][2], af[cur][mf][3],
                              bf[cur][nf][0], bf[cur][nf][1]);
        }
        stage++; if (stage >= STAGES) stage = 0;
    }

    // ---- epilogue: h tile -> smem (clip(acc/4064 + b1)), then fused fc2 partial ----
    __syncthreads();   // everyone done reading stage smem before overwrite
    float* hs = (float*)dsm;
    const float SCL = (float)(1.0 / 4064.0);
    const int rloc0 = wm * 64 + (lane >> 2);
    const int cloc0 = wn * 64 + (lane & 3) * 2;
#pragma unroll
    for (int mf = 0; mf < 4; mf++) {
#pragma unroll
        for (int nf = 0; nf < 8; nf++) {
            int cl = cloc0 + nf * 8;
            float bb0 = __ldg(b1 + n0 + cl), bb1 = __ldg(b1 + n0 + cl + 1);
#pragma unroll
            for (int half = 0; half < 2; half++) {
                int rl = rloc0 + mf * 16 + half * 8;
                float v0 = fmaf((float)acc[mf][nf][2 * half],     SCL, bb0);
                float v1 = fmaf((float)acc[mf][nf][2 * half + 1], SCL, bb1);
                v0 = fminf(1.0f, fmaxf(-1.0f, v0));
                v1 = fminf(1.0f, fmaxf(-1.0f, v1));
                *(float2*)(hs + rl * HS + cl) = make_float2(v0, v1);
            }
        }
    }
    __syncthreads();

    // fc2 partial: thread t owns row t; W2 loads warp-uniform (L1-resident)
    {
        float accf[OUTF];
#pragma unroll
        for (int o = 0; o < OUTF; o++) accf[o] = 0.0f;
        const float4* hv4 = (const float4*)(hs + tid * HS);
        const float4* W2v = (const float4*)W2;
        const int base = n0 >> 2;
#pragma unroll 4
        for (int c4 = 0; c4 < 32; c4++) {
            float4 h4 = hv4[c4];
#pragma unroll
            for (int o = 0; o < OUTF; o++) {
                float4 w = __ldg(&W2v[o * (HID / 4) + base + c4]);
                accf[o] += h4.x * w.x + h4.y * w.y + h4.z * w.z + h4.w * w.w;
            }
        }
        float* op = out + (size_t)(m0 + tid) * OUTF;
#pragma unroll
        for (int o = 0; o < OUTF; o++) atomicAdd(op + o, accf[o]);
    }
}

// -------------------- launch --------------------
extern "C" void kernel_launch(void* const* d_in, const int* in_sizes, int n_in,
                              void* d_out, int out_size) {
    const float* x  = (const float*)d_in[0];
    const float* W1 = (const float*)d_in[1];
    const float* b1 = (const float*)d_in[2];
    const float* W2 = (const float*)d_in[3];
    const float* b2 = (const float*)d_in[4];
    float* out = (float*)d_out;

    cudaFuncSetAttribute(gemm1_kernel, cudaFuncAttributeMaxDynamicSharedMemorySize, SMEM_TOTAL);

    init_out_kernel<<<(BATCH * OUTF + 255) / 256, 256>>>(b2, out);
    prep_x_kernel<<<(BATCH * 216 + 255) / 256, 256>>>(x);
    prep_w_kernel<<<(HID * 200 + 255) / 256, 256>>>(W1);
    gemm1_kernel<<<dim3(BATCH / BM, HID / BN), 128, SMEM_TOTAL>>>(b1, W2, out);
}